// round 7
// baseline (speedup 1.0000x reference)
#include <cuda_runtime.h>
#include <cstdint>

// Problem constants (fixed by the dataset)
#define NODES 100000
#define RELS  8
#define HF    128          // input feature dim
#define HT    128          // output feature dim
#define NNZ   1600000

// ---------------- scratch (__device__ globals; no allocations allowed) ------
__device__ float g_H[(size_t)RELS * NODES * HT];   // 409.6 MB: H[r][n][k] = nodes[n]·W[r][k]
__device__ int   g_deg[NODES];
__device__ int   g_off[NODES + 1];
__device__ int   g_cursor[NODES];
__device__ int   g_epk[NNZ];                        // src | (rel<<17)
__device__ float g_ev[NNZ];

// ---------------- CSR build --------------------------------------------------
__global__ void k_zero_deg() {
    int i = blockIdx.x * blockDim.x + threadIdx.x;
    if (i < NODES) g_deg[i] = 0;
}

__global__ void k_count(const int* __restrict__ rows) {
    int e = blockIdx.x * blockDim.x + threadIdx.x;
    if (e >= NNZ) return;
    int r = rows[e];
    if (r < 0 || r >= NODES * RELS) return;   // guard: never fault on bad data
    int dst = r % NODES;
    atomicAdd(&g_deg[dst], 1);
}

// single-block exclusive scan over g_deg -> g_off / g_cursor
__global__ void k_scan() {
    __shared__ int s[1024];
    int tid = threadIdx.x;
    int carry = 0;
    const int nch = (NODES + 1023) / 1024;
    for (int c = 0; c < nch; c++) {
        int idx = c * 1024 + tid;
        int v = (idx < NODES) ? g_deg[idx] : 0;
        s[tid] = v;
        __syncthreads();
        #pragma unroll
        for (int off = 1; off < 1024; off <<= 1) {
            int t = (tid >= off) ? s[tid - off] : 0;
            __syncthreads();
            s[tid] += t;
            __syncthreads();
        }
        int inc = s[tid];
        int total = s[1023];
        int ex = carry + inc - v;
        if (idx < NODES) { g_off[idx] = ex; g_cursor[idx] = ex; }
        carry += total;
        __syncthreads();
    }
    if (tid == 0) g_off[NODES] = carry;
}

__global__ void k_scatter(const int* __restrict__ rows,
                          const int* __restrict__ cols,
                          const float* __restrict__ vals) {
    int e = blockIdx.x * blockDim.x + threadIdx.x;
    if (e >= NNZ) return;
    int r   = rows[e];
    int src = cols[e];
    if (r < 0 || r >= NODES * RELS) return;           // guards: skip, don't fault
    if (src < 0 || src >= NODES) return;
    int dst = r % NODES;
    int rel = r / NODES;
    int pos = atomicAdd(&g_cursor[dst], 1);
    g_epk[pos] = src | (rel << 17);
    g_ev[pos]  = vals[e];
}

// ---------------- dense pre-transform: H[r][n][i] = sum_j nodes[n][j]*W[r][i][j]
// Tile: 128 (nodes) x 128 (outputs = one relation), K=128 fully in smem.
// Both tiles stored transposed [k][m] / [k][n], pitch 132 floats (float4-aligned).
#define GEMM_PITCH 132
__global__ __launch_bounds__(256, 1)
void k_gemm(const float* __restrict__ nodes, const float* __restrict__ weights) {
    extern __shared__ float smem[];
    float* As = smem;                    // [128][132]  As[k][m]
    float* Bs = smem + 128 * GEMM_PITCH; // [128][132]  Bs[k][n]

    const int tid = threadIdx.x;
    const int mb  = blockIdx.x;
    const int rel = blockIdx.y;

    // ---- load A tile (nodes rows mb*128..+127), transposed into As[k][m]
    {
        int mi   = tid >> 1;          // 0..127
        int half = tid & 1;
        int mglob = mb * 128 + mi;
        bool mv = (mglob < NODES);
        const float4* A4 = (const float4*)nodes;
        const float4* W4 = (const float4*)(weights + (size_t)rel * HF * HT);
        #pragma unroll
        for (int t = 0; t < 16; t++) {
            int f = half * 16 + t;    // float4 column 0..31
            float4 v = mv ? A4[(size_t)mglob * 32 + f] : make_float4(0.f,0.f,0.f,0.f);
            As[(4*f+0)*GEMM_PITCH + mi] = v.x;
            As[(4*f+1)*GEMM_PITCH + mi] = v.y;
            As[(4*f+2)*GEMM_PITCH + mi] = v.z;
            As[(4*f+3)*GEMM_PITCH + mi] = v.w;
            float4 w = W4[(size_t)mi * 32 + f];   // W[rel][i=mi][j]
            Bs[(4*f+0)*GEMM_PITCH + mi] = w.x;
            Bs[(4*f+1)*GEMM_PITCH + mi] = w.y;
            Bs[(4*f+2)*GEMM_PITCH + mi] = w.z;
            Bs[(4*f+3)*GEMM_PITCH + mi] = w.w;
        }
    }
    __syncthreads();

    const int tx = tid & 15;   // -> n (output feature)
    const int ty = tid >> 4;   // -> m (node)
    float acc[8][8];
    #pragma unroll
    for (int i = 0; i < 8; i++)
        #pragma unroll
        for (int j = 0; j < 8; j++) acc[i][j] = 0.f;

    const float4* As4 = (const float4*)As;   // row pitch 33 float4
    const float4* Bs4 = (const float4*)Bs;

    #pragma unroll 4
    for (int k = 0; k < 128; k++) {
        float4 a0 = As4[k * 33 + ty];
        float4 a1 = As4[k * 33 + 16 + ty];
        float4 b0 = Bs4[k * 33 + tx];
        float4 b1 = Bs4[k * 33 + 16 + tx];
        float a[8] = {a0.x,a0.y,a0.z,a0.w,a1.x,a1.y,a1.z,a1.w};
        float b[8] = {b0.x,b0.y,b0.z,b0.w,b1.x,b1.y,b1.z,b1.w};
        #pragma unroll
        for (int i = 0; i < 8; i++)
            #pragma unroll
            for (int j = 0; j < 8; j++)
                acc[i][j] = fmaf(a[i], b[j], acc[i][j]);
    }

    float* Hrel = g_H + (size_t)rel * NODES * HT;
    #pragma unroll
    for (int im = 0; im < 8; im++) {
        int m = mb * 128 + ((im < 4) ? (ty * 4 + im) : (64 + ty * 4 + im - 4));
        if (m < NODES) {
            float4* o4 = (float4*)(Hrel + (size_t)m * HT);
            o4[tx]      = make_float4(acc[im][0], acc[im][1], acc[im][2], acc[im][3]);
            o4[16 + tx] = make_float4(acc[im][4], acc[im][5], acc[im][6], acc[im][7]);
        }
    }
}

// ---------------- gather: out[n] = relu( sum_{edges to n} val * H[rel][src] )
// one warp per node, float4 per lane (32 lanes * 4 = 128 features)
__global__ __launch_bounds__(256)
void k_gather(float* __restrict__ out) {
    int lane = threadIdx.x & 31;
    int n = blockIdx.x * 8 + (threadIdx.x >> 5);
    if (n >= NODES) return;

    int start = g_off[n];
    int end   = g_off[n + 1];
    float4 acc = make_float4(0.f, 0.f, 0.f, 0.f);
    const float4* H4 = (const float4*)g_H;

    int e = start;
    for (; e + 1 < end; e += 2) {
        int   pk0 = g_epk[e];
        float v0  = g_ev[e];
        int   pk1 = g_epk[e + 1];
        float v1  = g_ev[e + 1];
        int s0 = pk0 & 0x1FFFF, r0 = (pk0 >> 17) & 7;
        int s1 = pk1 & 0x1FFFF, r1 = (pk1 >> 17) & 7;
        float4 h0 = H4[((size_t)r0 * NODES + s0) * 32 + lane];
        float4 h1 = H4[((size_t)r1 * NODES + s1) * 32 + lane];
        acc.x = fmaf(v0, h0.x, acc.x); acc.y = fmaf(v0, h0.y, acc.y);
        acc.z = fmaf(v0, h0.z, acc.z); acc.w = fmaf(v0, h0.w, acc.w);
        acc.x = fmaf(v1, h1.x, acc.x); acc.y = fmaf(v1, h1.y, acc.y);
        acc.z = fmaf(v1, h1.z, acc.z); acc.w = fmaf(v1, h1.w, acc.w);
    }
    if (e < end) {
        int   pk = g_epk[e];
        float v  = g_ev[e];
        int s = pk & 0x1FFFF, r = (pk >> 17) & 7;
        float4 h = H4[((size_t)r * NODES + s) * 32 + lane];
        acc.x = fmaf(v, h.x, acc.x); acc.y = fmaf(v, h.y, acc.y);
        acc.z = fmaf(v, h.z, acc.z); acc.w = fmaf(v, h.w, acc.w);
    }

    float4 o;
    o.x = fmaxf(acc.x, 0.f); o.y = fmaxf(acc.y, 0.f);
    o.z = fmaxf(acc.z, 0.f); o.w = fmaxf(acc.w, 0.f);
    ((float4*)out)[(size_t)n * 32 + lane] = o;
}

// ---------------- launch -----------------------------------------------------
extern "C" void kernel_launch(void* const* d_in, const int* in_sizes, int n_in,
                              void* d_out, int out_size) {
    const float* nodes   = (const float*)d_in[0];
    const int*   indices = (const int*)d_in[1];   // int32! JAX x64 is disabled,
                                                  // astype(int64) yields int32.
    const float* values  = (const float*)d_in[2];
    const float* weights = (const float*)d_in[3];
    float*       out     = (float*)d_out;

    const int* rows = indices;         // indices is [2, NNZ] int32: rows then cols
    const int* cols = indices + NNZ;

    const int smem_bytes = 2 * 128 * GEMM_PITCH * (int)sizeof(float); // 135168
    cudaFuncSetAttribute(k_gemm, cudaFuncAttributeMaxDynamicSharedMemorySize, smem_bytes);

    // dense pre-transform H = nodes @ W_r^T for all relations
    dim3 ggrid((NODES + 127) / 128, RELS);
    k_gemm<<<ggrid, 256, smem_bytes>>>(nodes, weights);

    // CSR-by-destination build
    k_zero_deg<<<(NODES + 255) / 256, 256>>>();
    k_count<<<(NNZ + 255) / 256, 256>>>(rows);
    k_scan<<<1, 1024>>>();
    k_scatter<<<(NNZ + 255) / 256, 256>>>(rows, cols, values);

    // atomic-free aggregation + relu
    k_gather<<<(NODES + 7) / 8, 256>>>(out);
}

// round 10
// speedup vs baseline: 2.2041x; 2.2041x over previous
#include <cuda_runtime.h>
#include <cuda_bf16.h>
#include <cstdint>
#include <cstring>

// Problem constants (fixed by the dataset)
#define NODES 100000
#define RELS  8
#define HF    128
#define HT    128
#define NNZ   1600000
#define DEGPAD 102400            // NODES padded to int4 multiple for the scan
#define MBLK  ((NODES + 127) / 128)

// ---------------- scratch (__device__ globals; no allocations allowed) ------
__device__ float          g_H[(size_t)RELS * NODES * HT];  // H[r][n][i] fp32
__device__ __nv_bfloat16  g_Wh[RELS * HF * HT];            // weights hi (bf16)
__device__ __nv_bfloat16  g_Wl[RELS * HF * HT];            // weights lo (bf16)
__device__ int   g_deg[DEGPAD];
__device__ int   g_off[DEGPAD];
__device__ int   g_cursor[DEGPAD];
__device__ int   g_epk[NNZ];                                // src | (rel<<17)
__device__ float g_ev[NNZ];

// ---------------- helpers ----------------------------------------------------
__device__ __forceinline__ uint32_t smem_u32(const void* p) {
    uint32_t a;
    asm("{ .reg .u64 t; cvta.to.shared.u64 t, %1; cvt.u32.u64 %0, t; }"
        : "=r"(a) : "l"(p));
    return a;
}

__device__ __forceinline__ void ldsm_x4(uint32_t* r, uint32_t addr) {
    asm volatile("ldmatrix.sync.aligned.m8n8.x4.shared.b16 {%0,%1,%2,%3}, [%4];"
                 : "=r"(r[0]), "=r"(r[1]), "=r"(r[2]), "=r"(r[3]) : "r"(addr));
}

__device__ __forceinline__ void mma16816(float* c, const uint32_t* a,
                                         const uint32_t* b) {
    asm volatile(
        "mma.sync.aligned.m16n8k16.row.col.f32.bf16.bf16.f32 "
        "{%0,%1,%2,%3}, {%4,%5,%6,%7}, {%8,%9}, {%0,%1,%2,%3};"
        : "+f"(c[0]), "+f"(c[1]), "+f"(c[2]), "+f"(c[3])
        : "r"(a[0]), "r"(a[1]), "r"(a[2]), "r"(a[3]), "r"(b[0]), "r"(b[1]));
}

// ---------------- weight split: fp32 -> bf16 hi/lo ---------------------------
__global__ void k_wsplit(const float* __restrict__ weights) {
    int i = blockIdx.x * blockDim.x + threadIdx.x;
    if (i >= RELS * HF * HT) return;
    float w = weights[i];
    __nv_bfloat16 h = __float2bfloat16_rn(w);
    g_Wh[i] = h;
    g_Wl[i] = __float2bfloat16_rn(w - __bfloat162float(h));
}

// ---------------- tensor-core pre-transform via mma.sync ---------------------
// H[r][n][i] = sum_j nodes[n][j] * W[r][i][j]
// A = nodes tile [128 x 128] (row-major, k contiguous)     -> "row"
// B = W[r]      [128 x 128] (i rows, k contiguous = col-major KxN) -> "col"
// Split-bf16: D = Ah*Bh + Al*Bh + Ah*Bl  (~fp32 accuracy)
#define PITCH 136                       // bf16 per smem row (272 B, ldsm conflict-free)
#define TILE_B (128 * PITCH * 2)        // 34816 bytes per tile
#define SM_AH 0
#define SM_AL TILE_B
#define SM_BH (2 * TILE_B)
#define SM_BL (3 * TILE_B)
#define GEMM_SMEM (4 * TILE_B)          // 139264 B

__global__ __launch_bounds__(256, 1)
void k_gemm_tc(const float* __restrict__ nodes) {
    extern __shared__ char smem[];
    const uint32_t sbase = smem_u32(smem);

    const int tid  = threadIdx.x;
    const int lane = tid & 31;
    const int wid  = tid >> 5;
    const int mb   = blockIdx.x;

    // ---- convert + stage A tile (hi/lo) once --------------------------------
    #pragma unroll
    for (int t = 0; t < 16; t++) {
        int fi  = tid + t * 256;           // 0..4095 float4 slots
        int row = fi >> 5;
        int c4  = fi & 31;
        int gr  = mb * 128 + row;
        float4 v = (gr < NODES) ? ((const float4*)nodes)[(size_t)gr * 32 + c4]
                                : make_float4(0.f, 0.f, 0.f, 0.f);
        __nv_bfloat16 hx = __float2bfloat16_rn(v.x);
        __nv_bfloat16 hy = __float2bfloat16_rn(v.y);
        __nv_bfloat16 hz = __float2bfloat16_rn(v.z);
        __nv_bfloat16 hw = __float2bfloat16_rn(v.w);
        __nv_bfloat16 lx = __float2bfloat16_rn(v.x - __bfloat162float(hx));
        __nv_bfloat16 ly = __float2bfloat16_rn(v.y - __bfloat162float(hy));
        __nv_bfloat16 lz = __float2bfloat16_rn(v.z - __bfloat162float(hz));
        __nv_bfloat16 lw = __float2bfloat16_rn(v.w - __bfloat162float(hw));
        __nv_bfloat162 h0, h1, l0, l1;
        h0.x = hx; h0.y = hy; h1.x = hz; h1.y = hw;
        l0.x = lx; l0.y = ly; l1.x = lz; l1.y = lw;
        uint2 hu, lu;
        memcpy(&hu.x, &h0, 4); memcpy(&hu.y, &h1, 4);
        memcpy(&lu.x, &l0, 4); memcpy(&lu.y, &l1, 4);
        uint32_t off = (uint32_t)(row * PITCH + c4 * 4) * 2;
        *(uint2*)(smem + SM_AH + off) = hu;
        *(uint2*)(smem + SM_AL + off) = lu;
    }

    // warp tiling: 2 x 4 warp grid of 64x32 tiles
    const int warp_m = wid & 1;
    const int warp_n = wid >> 1;
    const int g = lane >> 2;               // output row group
    const int q = lane & 3;                // output col pair

    // ldmatrix lane addressing (A: m16k16 tiles; B: n16k16 tiles)
    const int a_row = (lane & 7) + ((lane >> 3) & 1) * 8;
    const int a_k8  = (lane >> 4) * 8;
    const int b_n   = (lane & 7) + (lane >> 4) * 8;
    const int b_k8  = ((lane >> 3) & 1) * 8;

    for (int rel = 0; rel < RELS; rel++) {
        // ---- stage B tile (hi/lo) for this relation -------------------------
        const uint2* Wh2 = (const uint2*)g_Wh;
        const uint2* Wl2 = (const uint2*)g_Wl;
        #pragma unroll
        for (int t = 0; t < 16; t++) {
            int fi  = tid + t * 256;       // i*32 + q4
            int row = fi >> 5;
            int c4  = fi & 31;
            uint32_t off = (uint32_t)(row * PITCH + c4 * 4) * 2;
            *(uint2*)(smem + SM_BH + off) = Wh2[rel * 4096 + fi];
            *(uint2*)(smem + SM_BL + off) = Wl2[rel * 4096 + fi];
        }
        __syncthreads();

        float acc[4][4][4];
        #pragma unroll
        for (int mi = 0; mi < 4; mi++)
            #pragma unroll
            for (int ni = 0; ni < 4; ni++)
                #pragma unroll
                for (int e = 0; e < 4; e++) acc[mi][ni][e] = 0.f;

        #pragma unroll
        for (int ks = 0; ks < 8; ks++) {
            const int kb = ks * 16;
            uint32_t ah[4][4], al[4][4];
            #pragma unroll
            for (int mi = 0; mi < 4; mi++) {
                int r = warp_m * 64 + mi * 16 + a_row;
                uint32_t ad = sbase + (uint32_t)(r * PITCH + kb + a_k8) * 2;
                ldsm_x4(ah[mi], ad + SM_AH);
                ldsm_x4(al[mi], ad + SM_AL);
            }
            uint32_t bh[2][4], bl[2][4];
            #pragma unroll
            for (int nj = 0; nj < 2; nj++) {
                int n = warp_n * 32 + nj * 16 + b_n;
                uint32_t ad = sbase + (uint32_t)(n * PITCH + kb + b_k8) * 2;
                ldsm_x4(bh[nj], ad + SM_BH);
                ldsm_x4(bl[nj], ad + SM_BL);
            }
            #pragma unroll
            for (int mi = 0; mi < 4; mi++)
                #pragma unroll
                for (int ni = 0; ni < 4; ni++) {
                    const uint32_t* fh = &bh[ni >> 1][(ni & 1) * 2];
                    const uint32_t* fl = &bl[ni >> 1][(ni & 1) * 2];
                    mma16816(acc[mi][ni], ah[mi], fh);   // Ah*Bh
                    mma16816(acc[mi][ni], al[mi], fh);   // Al*Bh
                    mma16816(acc[mi][ni], ah[mi], fl);   // Ah*Bl
                }
        }

        // ---- write D tile to g_H -------------------------------------------
        float* Hrel = g_H + (size_t)rel * NODES * HT;
        #pragma unroll
        for (int mi = 0; mi < 4; mi++) {
            int r0 = mb * 128 + warp_m * 64 + mi * 16 + g;
            int r1 = r0 + 8;
            #pragma unroll
            for (int ni = 0; ni < 4; ni++) {
                int col = warp_n * 32 + ni * 8 + q * 2;
                if (r0 < NODES)
                    *(float2*)&Hrel[(size_t)r0 * HT + col] =
                        make_float2(acc[mi][ni][0], acc[mi][ni][1]);
                if (r1 < NODES)
                    *(float2*)&Hrel[(size_t)r1 * HT + col] =
                        make_float2(acc[mi][ni][2], acc[mi][ni][3]);
            }
        }
        __syncthreads();   // protect B smem before next relation's load
    }
}

// ---------------- CSR build --------------------------------------------------
__global__ void k_zero_deg() {
    int i = blockIdx.x * blockDim.x + threadIdx.x;
    if (i < DEGPAD) g_deg[i] = 0;
}

__global__ void k_count(const int* __restrict__ rows) {
    int e = blockIdx.x * blockDim.x + threadIdx.x;
    if (e >= NNZ) return;
    int r = rows[e];
    if (r < 0 || r >= NODES * RELS) return;
    atomicAdd(&g_deg[r % NODES], 1);
}

// single-block warp-shuffle exclusive scan over g_deg -> g_off / g_cursor
__global__ void k_scan() {
    __shared__ int wsum[32];
    __shared__ int s_total;
    int tid = threadIdx.x, lane = tid & 31, wid = tid >> 5;
    int carry = 0;
    for (int base = 0; base < NODES; base += 4096) {
        int idx = base + tid * 4;
        int4 v = *(const int4*)&g_deg[idx];
        int sum = v.x + v.y + v.z + v.w;
        int incl = sum;
        #pragma unroll
        for (int o = 1; o < 32; o <<= 1) {
            int n = __shfl_up_sync(0xffffffffu, incl, o);
            if (lane >= o) incl += n;
        }
        if (lane == 31) wsum[wid] = incl;
        __syncthreads();
        if (wid == 0) {
            int ws = wsum[lane];
            int wi = ws;
            #pragma unroll
            for (int o = 1; o < 32; o <<= 1) {
                int n = __shfl_up_sync(0xffffffffu, wi, o);
                if (lane >= o) wi += n;
            }
            wsum[lane] = wi - ws;                 // exclusive warp offsets
            if (lane == 31) s_total = wi;         // chunk total
        }
        __syncthreads();
        int ex = carry + wsum[wid] + (incl - sum);
        int4 o;
        o.x = ex; o.y = ex + v.x; o.z = o.y + v.y; o.w = o.z + v.z;
        *(int4*)&g_off[idx]    = o;
        *(int4*)&g_cursor[idx] = o;
        carry += s_total;
        __syncthreads();
    }
}

__global__ void k_scatter(const int* __restrict__ rows,
                          const int* __restrict__ cols,
                          const float* __restrict__ vals) {
    int e = blockIdx.x * blockDim.x + threadIdx.x;
    if (e >= NNZ) return;
    int r   = rows[e];
    int src = cols[e];
    if (r < 0 || r >= NODES * RELS) return;
    if (src < 0 || src >= NODES) return;
    int dst = r % NODES;
    int rel = r / NODES;
    int pos = atomicAdd(&g_cursor[dst], 1);
    g_epk[pos] = src | (rel << 17);
    g_ev[pos]  = vals[e];
}

// ---------------- gather: out[n] = relu( sum val * H[rel][src] ) --------------
__global__ __launch_bounds__(256)
void k_gather(float* __restrict__ out) {
    int lane = threadIdx.x & 31;
    int n = blockIdx.x * 8 + (threadIdx.x >> 5);
    if (n >= NODES) return;

    int start = g_off[n];
    int end   = g_off[n + 1];
    float4 acc = make_float4(0.f, 0.f, 0.f, 0.f);
    const float4* H4 = (const float4*)g_H;

    int e = start;
    for (; e + 1 < end; e += 2) {
        int   pk0 = g_epk[e];
        float v0  = g_ev[e];
        int   pk1 = g_epk[e + 1];
        float v1  = g_ev[e + 1];
        int s0 = pk0 & 0x1FFFF, r0 = (pk0 >> 17) & 7;
        int s1 = pk1 & 0x1FFFF, r1 = (pk1 >> 17) & 7;
        float4 h0 = H4[((size_t)r0 * NODES + s0) * 32 + lane];
        float4 h1 = H4[((size_t)r1 * NODES + s1) * 32 + lane];
        acc.x = fmaf(v0, h0.x, acc.x); acc.y = fmaf(v0, h0.y, acc.y);
        acc.z = fmaf(v0, h0.z, acc.z); acc.w = fmaf(v0, h0.w, acc.w);
        acc.x = fmaf(v1, h1.x, acc.x); acc.y = fmaf(v1, h1.y, acc.y);
        acc.z = fmaf(v1, h1.z, acc.z); acc.w = fmaf(v1, h1.w, acc.w);
    }
    if (e < end) {
        int   pk = g_epk[e];
        float v  = g_ev[e];
        int s = pk & 0x1FFFF, r = (pk >> 17) & 7;
        float4 h = H4[((size_t)r * NODES + s) * 32 + lane];
        acc.x = fmaf(v, h.x, acc.x); acc.y = fmaf(v, h.y, acc.y);
        acc.z = fmaf(v, h.z, acc.z); acc.w = fmaf(v, h.w, acc.w);
    }

    float4 o;
    o.x = fmaxf(acc.x, 0.f); o.y = fmaxf(acc.y, 0.f);
    o.z = fmaxf(acc.z, 0.f); o.w = fmaxf(acc.w, 0.f);
    ((float4*)out)[(size_t)n * 32 + lane] = o;
}

// ---------------- launch -----------------------------------------------------
extern "C" void kernel_launch(void* const* d_in, const int* in_sizes, int n_in,
                              void* d_out, int out_size) {
    const float* nodes   = (const float*)d_in[0];
    const int*   indices = (const int*)d_in[1];   // int32 (JAX x64 disabled)
    const float* values  = (const float*)d_in[2];
    const float* weights = (const float*)d_in[3];
    float*       out     = (float*)d_out;

    const int* rows = indices;
    const int* cols = indices + NNZ;

    cudaFuncSetAttribute(k_gemm_tc, cudaFuncAttributeMaxDynamicSharedMemorySize,
                         GEMM_SMEM);

    // weight split + tensor-core pre-transform H[r] = nodes @ W_r^T
    k_wsplit<<<(RELS * HF * HT + 255) / 256, 256>>>(weights);
    k_gemm_tc<<<MBLK, 256, GEMM_SMEM>>>(nodes);

    // CSR-by-destination build
    k_zero_deg<<<(DEGPAD + 255) / 256, 256>>>();
    k_count<<<(NNZ + 255) / 256, 256>>>(rows);
    k_scan<<<1, 1024>>>();
    k_scatter<<<(NNZ + 255) / 256, 256>>>(rows, cols, values);

    // atomic-free aggregation + relu
    k_gather<<<(NODES + 7) / 8, 256>>>(out);
}

// round 11
// speedup vs baseline: 2.6542x; 1.2042x over previous
#include <cuda_runtime.h>
#include <cuda_bf16.h>
#include <cuda_fp16.h>
#include <cstdint>
#include <cstring>

// Problem constants (fixed by the dataset)
#define NODES 100000
#define RELS  8
#define HF    128
#define HT    128
#define NNZ   1600000
#define DEGPAD 102400            // NODES padded to int4 multiple for the scan
#define MBLK  ((NODES + 127) / 128)

// ---------------- scratch (__device__ globals; no allocations allowed) ------
__device__ __half         g_H[(size_t)RELS * NODES * HT];  // 204.8 MB fp16
__device__ __nv_bfloat16  g_Wh[RELS * HF * HT];            // weights hi (bf16)
__device__ __nv_bfloat16  g_Wl[RELS * HF * HT];            // weights lo (bf16)
__device__ int   g_deg[DEGPAD];
__device__ int   g_off[DEGPAD];
__device__ int   g_cursor[DEGPAD];
__device__ int2  g_e[NNZ];       // {src | rel<<17, val bits}

// ---------------- helpers ----------------------------------------------------
__device__ __forceinline__ uint32_t smem_u32(const void* p) {
    uint32_t a;
    asm("{ .reg .u64 t; cvta.to.shared.u64 t, %1; cvt.u32.u64 %0, t; }"
        : "=r"(a) : "l"(p));
    return a;
}

__device__ __forceinline__ void ldsm_x4(uint32_t* r, uint32_t addr) {
    asm volatile("ldmatrix.sync.aligned.m8n8.x4.shared.b16 {%0,%1,%2,%3}, [%4];"
                 : "=r"(r[0]), "=r"(r[1]), "=r"(r[2]), "=r"(r[3]) : "r"(addr));
}

__device__ __forceinline__ void mma16816(float* c, const uint32_t* a,
                                         const uint32_t* b) {
    asm volatile(
        "mma.sync.aligned.m16n8k16.row.col.f32.bf16.bf16.f32 "
        "{%0,%1,%2,%3}, {%4,%5,%6,%7}, {%8,%9}, {%0,%1,%2,%3};"
        : "+f"(c[0]), "+f"(c[1]), "+f"(c[2]), "+f"(c[3])
        : "r"(a[0]), "r"(a[1]), "r"(a[2]), "r"(a[3]), "r"(b[0]), "r"(b[1]));
}

// ---------------- weight split: fp32 -> bf16 hi/lo ---------------------------
__global__ void k_wsplit(const float* __restrict__ weights) {
    int i = blockIdx.x * blockDim.x + threadIdx.x;
    if (i >= RELS * HF * HT) return;
    float w = weights[i];
    __nv_bfloat16 h = __float2bfloat16_rn(w);
    g_Wh[i] = h;
    g_Wl[i] = __float2bfloat16_rn(w - __bfloat162float(h));
}

// ---------------- tensor-core pre-transform via mma.sync ---------------------
// H[r][n][i] = sum_j nodes[n][j] * W[r][i][j]   (fp16 output)
// Split-bf16: D = Ah*Bh + Al*Bh + Ah*Bl  (~fp32 accuracy in the GEMM itself)
#define PITCH 136                       // bf16 per smem row (272 B, ldsm conflict-free)
#define TILE_B (128 * PITCH * 2)        // 34816 bytes per tile
#define SM_AH 0
#define SM_AL TILE_B
#define SM_BH (2 * TILE_B)
#define SM_BL (3 * TILE_B)
#define GEMM_SMEM (4 * TILE_B)          // 139264 B

__global__ __launch_bounds__(256, 1)
void k_gemm_tc(const float* __restrict__ nodes) {
    extern __shared__ char smem[];
    const uint32_t sbase = smem_u32(smem);

    const int tid  = threadIdx.x;
    const int lane = tid & 31;
    const int wid  = tid >> 5;
    const int mb   = blockIdx.x;

    // ---- convert + stage A tile (hi/lo) once --------------------------------
    #pragma unroll
    for (int t = 0; t < 16; t++) {
        int fi  = tid + t * 256;           // 0..4095 float4 slots
        int row = fi >> 5;
        int c4  = fi & 31;
        int gr  = mb * 128 + row;
        float4 v = (gr < NODES) ? ((const float4*)nodes)[(size_t)gr * 32 + c4]
                                : make_float4(0.f, 0.f, 0.f, 0.f);
        __nv_bfloat16 hx = __float2bfloat16_rn(v.x);
        __nv_bfloat16 hy = __float2bfloat16_rn(v.y);
        __nv_bfloat16 hz = __float2bfloat16_rn(v.z);
        __nv_bfloat16 hw = __float2bfloat16_rn(v.w);
        __nv_bfloat16 lx = __float2bfloat16_rn(v.x - __bfloat162float(hx));
        __nv_bfloat16 ly = __float2bfloat16_rn(v.y - __bfloat162float(hy));
        __nv_bfloat16 lz = __float2bfloat16_rn(v.z - __bfloat162float(hz));
        __nv_bfloat16 lw = __float2bfloat16_rn(v.w - __bfloat162float(hw));
        __nv_bfloat162 h0, h1, l0, l1;
        h0.x = hx; h0.y = hy; h1.x = hz; h1.y = hw;
        l0.x = lx; l0.y = ly; l1.x = lz; l1.y = lw;
        uint2 hu, lu;
        memcpy(&hu.x, &h0, 4); memcpy(&hu.y, &h1, 4);
        memcpy(&lu.x, &l0, 4); memcpy(&lu.y, &l1, 4);
        uint32_t off = (uint32_t)(row * PITCH + c4 * 4) * 2;
        *(uint2*)(smem + SM_AH + off) = hu;
        *(uint2*)(smem + SM_AL + off) = lu;
    }

    // warp tiling: 2 x 4 warp grid of 64x32 tiles
    const int warp_m = wid & 1;
    const int warp_n = wid >> 1;
    const int g = lane >> 2;               // output row group
    const int q = lane & 3;                // output col pair

    // ldmatrix lane addressing (A: m16k16 tiles; B: n16k16 tiles)
    const int a_row = (lane & 7) + ((lane >> 3) & 1) * 8;
    const int a_k8  = (lane >> 4) * 8;
    const int b_n   = (lane & 7) + (lane >> 4) * 8;
    const int b_k8  = ((lane >> 3) & 1) * 8;

    for (int rel = 0; rel < RELS; rel++) {
        // ---- stage B tile (hi/lo) for this relation -------------------------
        const uint2* Wh2 = (const uint2*)g_Wh;
        const uint2* Wl2 = (const uint2*)g_Wl;
        #pragma unroll
        for (int t = 0; t < 16; t++) {
            int fi  = tid + t * 256;       // i*32 + c4
            int row = fi >> 5;
            int c4  = fi & 31;
            uint32_t off = (uint32_t)(row * PITCH + c4 * 4) * 2;
            *(uint2*)(smem + SM_BH + off) = Wh2[rel * 4096 + fi];
            *(uint2*)(smem + SM_BL + off) = Wl2[rel * 4096 + fi];
        }
        __syncthreads();

        float acc[4][4][4];
        #pragma unroll
        for (int mi = 0; mi < 4; mi++)
            #pragma unroll
            for (int ni = 0; ni < 4; ni++)
                #pragma unroll
                for (int e = 0; e < 4; e++) acc[mi][ni][e] = 0.f;

        #pragma unroll
        for (int ks = 0; ks < 8; ks++) {
            const int kb = ks * 16;
            uint32_t ah[4][4], al[4][4];
            #pragma unroll
            for (int mi = 0; mi < 4; mi++) {
                int r = warp_m * 64 + mi * 16 + a_row;
                uint32_t ad = sbase + (uint32_t)(r * PITCH + kb + a_k8) * 2;
                ldsm_x4(ah[mi], ad + SM_AH);
                ldsm_x4(al[mi], ad + SM_AL);
            }
            uint32_t bh[2][4], bl[2][4];
            #pragma unroll
            for (int nj = 0; nj < 2; nj++) {
                int n = warp_n * 32 + nj * 16 + b_n;
                uint32_t ad = sbase + (uint32_t)(n * PITCH + kb + b_k8) * 2;
                ldsm_x4(bh[nj], ad + SM_BH);
                ldsm_x4(bl[nj], ad + SM_BL);
            }
            #pragma unroll
            for (int mi = 0; mi < 4; mi++)
                #pragma unroll
                for (int ni = 0; ni < 4; ni++) {
                    const uint32_t* fh = &bh[ni >> 1][(ni & 1) * 2];
                    const uint32_t* fl = &bl[ni >> 1][(ni & 1) * 2];
                    mma16816(acc[mi][ni], ah[mi], fh);   // Ah*Bh
                    mma16816(acc[mi][ni], al[mi], fh);   // Al*Bh
                    mma16816(acc[mi][ni], ah[mi], fl);   // Ah*Bl
                }
        }

        // ---- write D tile to g_H (fp16) ------------------------------------
        __half* Hrel = g_H + (size_t)rel * NODES * HT;
        #pragma unroll
        for (int mi = 0; mi < 4; mi++) {
            int r0 = mb * 128 + warp_m * 64 + mi * 16 + g;
            int r1 = r0 + 8;
            #pragma unroll
            for (int ni = 0; ni < 4; ni++) {
                int col = warp_n * 32 + ni * 8 + q * 2;
                if (r0 < NODES)
                    *(__half2*)&Hrel[(size_t)r0 * HT + col] =
                        __floats2half2_rn(acc[mi][ni][0], acc[mi][ni][1]);
                if (r1 < NODES)
                    *(__half2*)&Hrel[(size_t)r1 * HT + col] =
                        __floats2half2_rn(acc[mi][ni][2], acc[mi][ni][3]);
            }
        }
        __syncthreads();   // protect B smem before next relation's load
    }
}

// ---------------- CSR build --------------------------------------------------
__global__ void k_zero_deg() {
    int i = blockIdx.x * blockDim.x + threadIdx.x;
    if (i * 4 < DEGPAD) ((int4*)g_deg)[i] = make_int4(0, 0, 0, 0);
}

__global__ void k_count(const int* __restrict__ rows) {
    int e = blockIdx.x * blockDim.x + threadIdx.x;
    if (e >= NNZ) return;
    int r = rows[e];
    if (r < 0 || r >= NODES * RELS) return;
    atomicAdd(&g_deg[r % NODES], 1);
}

// single-block warp-shuffle exclusive scan over g_deg -> g_off / g_cursor
__global__ void k_scan() {
    __shared__ int wsum[32];
    __shared__ int s_total;
    int tid = threadIdx.x, lane = tid & 31, wid = tid >> 5;
    int carry = 0;
    for (int base = 0; base < NODES; base += 4096) {
        int idx = base + tid * 4;
        int4 v = *(const int4*)&g_deg[idx];
        int sum = v.x + v.y + v.z + v.w;
        int incl = sum;
        #pragma unroll
        for (int o = 1; o < 32; o <<= 1) {
            int n = __shfl_up_sync(0xffffffffu, incl, o);
            if (lane >= o) incl += n;
        }
        if (lane == 31) wsum[wid] = incl;
        __syncthreads();
        if (wid == 0) {
            int ws = wsum[lane];
            int wi = ws;
            #pragma unroll
            for (int o = 1; o < 32; o <<= 1) {
                int n = __shfl_up_sync(0xffffffffu, wi, o);
                if (lane >= o) wi += n;
            }
            wsum[lane] = wi - ws;                 // exclusive warp offsets
            if (lane == 31) s_total = wi;         // chunk total
        }
        __syncthreads();
        int ex = carry + wsum[wid] + (incl - sum);
        int4 o;
        o.x = ex; o.y = ex + v.x; o.z = o.y + v.y; o.w = o.z + v.z;
        *(int4*)&g_off[idx]    = o;
        *(int4*)&g_cursor[idx] = o;
        carry += s_total;
        __syncthreads();
    }
}

__global__ void k_scatter(const int* __restrict__ rows,
                          const int* __restrict__ cols,
                          const float* __restrict__ vals) {
    int e = blockIdx.x * blockDim.x + threadIdx.x;
    if (e >= NNZ) return;
    int r   = rows[e];
    int src = cols[e];
    if (r < 0 || r >= NODES * RELS) return;
    if (src < 0 || src >= NODES) return;
    int dst = r % NODES;
    int rel = r / NODES;
    int pos = atomicAdd(&g_cursor[dst], 1);
    g_e[pos] = make_int2(src | (rel << 17), __float_as_int(vals[e]));
}

// ---------------- gather: out[n] = relu( sum val * H[rel][src] ) --------------
// one warp per node; fp16 H rows (256 B), uint2 per lane; unroll-4 for MLP
__device__ __forceinline__ void acc_edge(float4& acc, int pk, float v,
                                         const uint2* __restrict__ H2, int lane) {
    size_t row = (size_t)((pk >> 17) & 7) * NODES + (pk & 0x1FFFF);
    uint2 u = H2[row * 32 + lane];
    __half2 h01 = *(__half2*)&u.x;
    __half2 h23 = *(__half2*)&u.y;
    float2 f01 = __half22float2(h01);
    float2 f23 = __half22float2(h23);
    acc.x = fmaf(v, f01.x, acc.x);
    acc.y = fmaf(v, f01.y, acc.y);
    acc.z = fmaf(v, f23.x, acc.z);
    acc.w = fmaf(v, f23.y, acc.w);
}

__global__ __launch_bounds__(256)
void k_gather(float* __restrict__ out) {
    int lane = threadIdx.x & 31;
    int n = blockIdx.x * 8 + (threadIdx.x >> 5);
    if (n >= NODES) return;

    int start = g_off[n];
    int end   = g_off[n + 1];
    float4 acc = make_float4(0.f, 0.f, 0.f, 0.f);
    const uint2* H2 = (const uint2*)g_H;

    int e = start;
    for (; e + 3 < end; e += 4) {
        int2 e0 = g_e[e];
        int2 e1 = g_e[e + 1];
        int2 e2 = g_e[e + 2];
        int2 e3 = g_e[e + 3];
        acc_edge(acc, e0.x, __int_as_float(e0.y), H2, lane);
        acc_edge(acc, e1.x, __int_as_float(e1.y), H2, lane);
        acc_edge(acc, e2.x, __int_as_float(e2.y), H2, lane);
        acc_edge(acc, e3.x, __int_as_float(e3.y), H2, lane);
    }
    for (; e < end; e++) {
        int2 ed = g_e[e];
        acc_edge(acc, ed.x, __int_as_float(ed.y), H2, lane);
    }

    float4 o;
    o.x = fmaxf(acc.x, 0.f); o.y = fmaxf(acc.y, 0.f);
    o.z = fmaxf(acc.z, 0.f); o.w = fmaxf(acc.w, 0.f);
    ((float4*)out)[(size_t)n * 32 + lane] = o;
}

// ---------------- launch -----------------------------------------------------
extern "C" void kernel_launch(void* const* d_in, const int* in_sizes, int n_in,
                              void* d_out, int out_size) {
    const float* nodes   = (const float*)d_in[0];
    const int*   indices = (const int*)d_in[1];   // int32 (JAX x64 disabled)
    const float* values  = (const float*)d_in[2];
    const float* weights = (const float*)d_in[3];
    float*       out     = (float*)d_out;

    const int* rows = indices;
    const int* cols = indices + NNZ;

    cudaFuncSetAttribute(k_gemm_tc, cudaFuncAttributeMaxDynamicSharedMemorySize,
                         GEMM_SMEM);

    // weight split + tensor-core pre-transform H[r] = nodes @ W_r^T (fp16 out)
    k_wsplit<<<(RELS * HF * HT + 255) / 256, 256>>>(weights);
    k_gemm_tc<<<MBLK, 256, GEMM_SMEM>>>(nodes);

    // CSR-by-destination build
    k_zero_deg<<<(DEGPAD / 4 + 255) / 256, 256>>>();
    k_count<<<(NNZ + 255) / 256, 256>>>(rows);
    k_scan<<<1, 1024>>>();
    k_scatter<<<(NNZ + 255) / 256, 256>>>(rows, cols, values);

    // atomic-free aggregation + relu
    k_gather<<<(NODES + 7) / 8, 256>>>(out);
}

// round 12
// speedup vs baseline: 3.6373x; 1.3704x over previous
#include <cuda_runtime.h>
#include <cuda_fp16.h>
#include <cstdint>
#include <cstring>

// Problem constants (fixed by the dataset)
#define NODES 100000
#define RELS  8
#define HF    128
#define HT    128
#define NNZ   1600000
#define DEGPAD 102400            // NODES padded to int4 multiple for the scan
#define MBLK  ((NODES + 127) / 128)

// ---------------- scratch (__device__ globals; no allocations allowed) ------
__device__ __half g_H[(size_t)RELS * NODES * HT];  // 204.8 MB fp16
__device__ __half g_Wh[RELS * HF * HT];            // weights rounded to fp16
__device__ int   g_deg[DEGPAD];
__device__ int   g_off[DEGPAD];
__device__ int   g_cursor[DEGPAD];
__device__ int2  g_e[NNZ];       // {src | rel<<17, val bits}

// ---------------- helpers ----------------------------------------------------
__device__ __forceinline__ uint32_t smem_u32(const void* p) {
    uint32_t a;
    asm("{ .reg .u64 t; cvta.to.shared.u64 t, %1; cvt.u32.u64 %0, t; }"
        : "=r"(a) : "l"(p));
    return a;
}

__device__ __forceinline__ void ldsm_x4(uint32_t* r, uint32_t addr) {
    asm volatile("ldmatrix.sync.aligned.m8n8.x4.shared.b16 {%0,%1,%2,%3}, [%4];"
                 : "=r"(r[0]), "=r"(r[1]), "=r"(r[2]), "=r"(r[3]) : "r"(addr));
}

__device__ __forceinline__ void mma16816h(float* c, const uint32_t* a,
                                          const uint32_t* b) {
    asm volatile(
        "mma.sync.aligned.m16n8k16.row.col.f32.f16.f16.f32 "
        "{%0,%1,%2,%3}, {%4,%5,%6,%7}, {%8,%9}, {%0,%1,%2,%3};"
        : "+f"(c[0]), "+f"(c[1]), "+f"(c[2]), "+f"(c[3])
        : "r"(a[0]), "r"(a[1]), "r"(a[2]), "r"(a[3]), "r"(b[0]), "r"(b[1]));
}

// ---------------- weight round: fp32 -> fp16 ---------------------------------
__global__ void k_wsplit(const float* __restrict__ weights) {
    int i = blockIdx.x * blockDim.x + threadIdx.x;
    if (i >= RELS * HF * HT) return;
    g_Wh[i] = __float2half_rn(weights[i]);
}

// ---------------- tensor-core pre-transform via mma.sync ---------------------
// H[r][n][i] = sum_j nodes[n][j] * W[r][i][j]   (fp16 output)
// A split fp16 hi/lo (exact to ~2^-22); B rounded to fp16 once.
// D = Ah*Bh + Al*Bh  == A_exact * B_fp16
#define PITCH 136                       // fp16 per smem row (272 B, ldsm conflict-free)
#define TILE_B (128 * PITCH * 2)        // 34816 bytes per tile
#define SM_AH 0
#define SM_AL TILE_B
#define SM_BH (2 * TILE_B)
#define GEMM_SMEM (3 * TILE_B)          // 104448 B -> 2 CTAs/SM

__global__ __launch_bounds__(256, 2)
void k_gemm_tc(const float* __restrict__ nodes) {
    extern __shared__ char smem[];
    const uint32_t sbase = smem_u32(smem);

    const int tid  = threadIdx.x;
    const int lane = tid & 31;
    const int wid  = tid >> 5;
    const int mb   = blockIdx.x;

    // ---- convert + stage A tile (fp16 hi/lo) once ---------------------------
    #pragma unroll
    for (int t = 0; t < 16; t++) {
        int fi  = tid + t * 256;           // 0..4095 float4 slots
        int row = fi >> 5;
        int c4  = fi & 31;
        int gr  = mb * 128 + row;
        float4 v = (gr < NODES) ? ((const float4*)nodes)[(size_t)gr * 32 + c4]
                                : make_float4(0.f, 0.f, 0.f, 0.f);
        __half hx = __float2half_rn(v.x);
        __half hy = __float2half_rn(v.y);
        __half hz = __float2half_rn(v.z);
        __half hw = __float2half_rn(v.w);
        __half lx = __float2half_rn(v.x - __half2float(hx));
        __half ly = __float2half_rn(v.y - __half2float(hy));
        __half lz = __float2half_rn(v.z - __half2float(hz));
        __half lw = __float2half_rn(v.w - __half2float(hw));
        __half2 h0 = __halves2half2(hx, hy), h1 = __halves2half2(hz, hw);
        __half2 l0 = __halves2half2(lx, ly), l1 = __halves2half2(lz, lw);
        uint2 hu, lu;
        memcpy(&hu.x, &h0, 4); memcpy(&hu.y, &h1, 4);
        memcpy(&lu.x, &l0, 4); memcpy(&lu.y, &l1, 4);
        uint32_t off = (uint32_t)(row * PITCH + c4 * 4) * 2;
        *(uint2*)(smem + SM_AH + off) = hu;
        *(uint2*)(smem + SM_AL + off) = lu;
    }

    // warp tiling: 2 x 4 warp grid of 64x32 tiles
    const int warp_m = wid & 1;
    const int warp_n = wid >> 1;
    const int g = lane >> 2;               // output row group
    const int q = lane & 3;                // output col pair

    // ldmatrix lane addressing (A: m16k16 tiles; B: n16k16 tiles)
    const int a_row = (lane & 7) + ((lane >> 3) & 1) * 8;
    const int a_k8  = (lane >> 4) * 8;
    const int b_n   = (lane & 7) + (lane >> 4) * 8;
    const int b_k8  = ((lane >> 3) & 1) * 8;

    for (int rel = 0; rel < RELS; rel++) {
        // ---- stage B tile (fp16) for this relation --------------------------
        const uint2* Wh2 = (const uint2*)g_Wh;
        #pragma unroll
        for (int t = 0; t < 16; t++) {
            int fi  = tid + t * 256;       // i*32 + c4
            int row = fi >> 5;
            int c4  = fi & 31;
            uint32_t off = (uint32_t)(row * PITCH + c4 * 4) * 2;
            *(uint2*)(smem + SM_BH + off) = Wh2[rel * 4096 + fi];
        }
        __syncthreads();

        float acc[4][4][4];
        #pragma unroll
        for (int mi = 0; mi < 4; mi++)
            #pragma unroll
            for (int ni = 0; ni < 4; ni++)
                #pragma unroll
                for (int e = 0; e < 4; e++) acc[mi][ni][e] = 0.f;

        #pragma unroll
        for (int ks = 0; ks < 8; ks++) {
            const int kb = ks * 16;
            uint32_t ah[4][4], al[4][4];
            #pragma unroll
            for (int mi = 0; mi < 4; mi++) {
                int r = warp_m * 64 + mi * 16 + a_row;
                uint32_t ad = sbase + (uint32_t)(r * PITCH + kb + a_k8) * 2;
                ldsm_x4(ah[mi], ad + SM_AH);
                ldsm_x4(al[mi], ad + SM_AL);
            }
            uint32_t bh[2][4];
            #pragma unroll
            for (int nj = 0; nj < 2; nj++) {
                int n = warp_n * 32 + nj * 16 + b_n;
                uint32_t ad = sbase + (uint32_t)(n * PITCH + kb + b_k8) * 2;
                ldsm_x4(bh[nj], ad + SM_BH);
            }
            #pragma unroll
            for (int mi = 0; mi < 4; mi++)
                #pragma unroll
                for (int ni = 0; ni < 4; ni++) {
                    const uint32_t* fb = &bh[ni >> 1][(ni & 1) * 2];
                    mma16816h(acc[mi][ni], ah[mi], fb);   // Ah*B
                    mma16816h(acc[mi][ni], al[mi], fb);   // Al*B
                }
        }

        // ---- write D tile to g_H (fp16) ------------------------------------
        __half* Hrel = g_H + (size_t)rel * NODES * HT;
        #pragma unroll
        for (int mi = 0; mi < 4; mi++) {
            int r0 = mb * 128 + warp_m * 64 + mi * 16 + g;
            int r1 = r0 + 8;
            #pragma unroll
            for (int ni = 0; ni < 4; ni++) {
                int col = warp_n * 32 + ni * 8 + q * 2;
                if (r0 < NODES)
                    *(__half2*)&Hrel[(size_t)r0 * HT + col] =
                        __floats2half2_rn(acc[mi][ni][0], acc[mi][ni][1]);
                if (r1 < NODES)
                    *(__half2*)&Hrel[(size_t)r1 * HT + col] =
                        __floats2half2_rn(acc[mi][ni][2], acc[mi][ni][3]);
            }
        }
        __syncthreads();   // protect B smem before next relation's load
    }
}

// ---------------- CSR build --------------------------------------------------
__global__ void k_zero_deg() {
    int i = blockIdx.x * blockDim.x + threadIdx.x;
    if (i * 4 < DEGPAD) ((int4*)g_deg)[i] = make_int4(0, 0, 0, 0);
}

__global__ void k_count(const int* __restrict__ rows) {
    int e = blockIdx.x * blockDim.x + threadIdx.x;
    if (e >= NNZ) return;
    int r = rows[e];
    if (r < 0 || r >= NODES * RELS) return;
    atomicAdd(&g_deg[r % NODES], 1);
}

// single-block warp-shuffle exclusive scan over g_deg -> g_off / g_cursor
__global__ void k_scan() {
    __shared__ int wsum[32];
    __shared__ int s_total;
    int tid = threadIdx.x, lane = tid & 31, wid = tid >> 5;
    int carry = 0;
    for (int base = 0; base < NODES; base += 4096) {
        int idx = base + tid * 4;
        int4 v = *(const int4*)&g_deg[idx];
        int sum = v.x + v.y + v.z + v.w;
        int incl = sum;
        #pragma unroll
        for (int o = 1; o < 32; o <<= 1) {
            int n = __shfl_up_sync(0xffffffffu, incl, o);
            if (lane >= o) incl += n;
        }
        if (lane == 31) wsum[wid] = incl;
        __syncthreads();
        if (wid == 0) {
            int ws = wsum[lane];
            int wi = ws;
            #pragma unroll
            for (int o = 1; o < 32; o <<= 1) {
                int n = __shfl_up_sync(0xffffffffu, wi, o);
                if (lane >= o) wi += n;
            }
            wsum[lane] = wi - ws;                 // exclusive warp offsets
            if (lane == 31) s_total = wi;         // chunk total
        }
        __syncthreads();
        int ex = carry + wsum[wid] + (incl - sum);
        int4 o;
        o.x = ex; o.y = ex + v.x; o.z = o.y + v.y; o.w = o.z + v.z;
        *(int4*)&g_off[idx]    = o;
        *(int4*)&g_cursor[idx] = o;
        carry += s_total;
        __syncthreads();
    }
}

__global__ void k_scatter(const int* __restrict__ rows,
                          const int* __restrict__ cols,
                          const float* __restrict__ vals) {
    int e = blockIdx.x * blockDim.x + threadIdx.x;
    if (e >= NNZ) return;
    int r   = rows[e];
    int src = cols[e];
    if (r < 0 || r >= NODES * RELS) return;
    if (src < 0 || src >= NODES) return;
    int dst = r % NODES;
    int rel = r / NODES;
    int pos = atomicAdd(&g_cursor[dst], 1);
    g_e[pos] = make_int2(src | (rel << 17), __float_as_int(vals[e]));
}

// ---------------- gather: out[n] = relu( sum val * H[rel][src] ) --------------
// one warp per node; fp16 H rows (256 B), uint2 per lane; unroll-8, dual acc
__device__ __forceinline__ void acc_edge(float4& acc, int pk, float v,
                                         const uint2* __restrict__ H2, int lane) {
    size_t row = (size_t)((pk >> 17) & 7) * NODES + (pk & 0x1FFFF);
    uint2 u = H2[row * 32 + lane];
    __half2 h01 = *(__half2*)&u.x;
    __half2 h23 = *(__half2*)&u.y;
    float2 f01 = __half22float2(h01);
    float2 f23 = __half22float2(h23);
    acc.x = fmaf(v, f01.x, acc.x);
    acc.y = fmaf(v, f01.y, acc.y);
    acc.z = fmaf(v, f23.x, acc.z);
    acc.w = fmaf(v, f23.y, acc.w);
}

__global__ __launch_bounds__(256)
void k_gather(float* __restrict__ out) {
    int lane = threadIdx.x & 31;
    int n = blockIdx.x * 8 + (threadIdx.x >> 5);
    if (n >= NODES) return;

    int start = g_off[n];
    int end   = g_off[n + 1];
    float4 a0 = make_float4(0.f, 0.f, 0.f, 0.f);
    float4 a1 = make_float4(0.f, 0.f, 0.f, 0.f);
    const uint2* H2 = (const uint2*)g_H;
    const int4*  E4 = (const int4*)g_e;     // 2 edges per int4

    int e = start;
    for (; e + 7 < end; e += 8) {
        int j = e >> 1;                      // e is not 2-aligned in general; use
        // unaligned-safe path: g_e loads (int2) when e is odd
        if ((e & 1) == 0) {
            int4 p0 = E4[j], p1 = E4[j + 1], p2 = E4[j + 2], p3 = E4[j + 3];
            acc_edge(a0, p0.x, __int_as_float(p0.y), H2, lane);
            acc_edge(a1, p0.z, __int_as_float(p0.w), H2, lane);
            acc_edge(a0, p1.x, __int_as_float(p1.y), H2, lane);
            acc_edge(a1, p1.z, __int_as_float(p1.w), H2, lane);
            acc_edge(a0, p2.x, __int_as_float(p2.y), H2, lane);
            acc_edge(a1, p2.z, __int_as_float(p2.w), H2, lane);
            acc_edge(a0, p3.x, __int_as_float(p3.y), H2, lane);
            acc_edge(a1, p3.z, __int_as_float(p3.w), H2, lane);
        } else {
            int2 e0 = g_e[e],     e1 = g_e[e + 1], e2 = g_e[e + 2], e3 = g_e[e + 3];
            int2 e4 = g_e[e + 4], e5 = g_e[e + 5], e6 = g_e[e + 6], e7 = g_e[e + 7];
            acc_edge(a0, e0.x, __int_as_float(e0.y), H2, lane);
            acc_edge(a1, e1.x, __int_as_float(e1.y), H2, lane);
            acc_edge(a0, e2.x, __int_as_float(e2.y), H2, lane);
            acc_edge(a1, e3.x, __int_as_float(e3.y), H2, lane);
            acc_edge(a0, e4.x, __int_as_float(e4.y), H2, lane);
            acc_edge(a1, e5.x, __int_as_float(e5.y), H2, lane);
            acc_edge(a0, e6.x, __int_as_float(e6.y), H2, lane);
            acc_edge(a1, e7.x, __int_as_float(e7.y), H2, lane);
        }
    }
    for (; e < end; e++) {
        int2 ed = g_e[e];
        acc_edge(a0, ed.x, __int_as_float(ed.y), H2, lane);
    }

    float4 o;
    o.x = fmaxf(a0.x + a1.x, 0.f); o.y = fmaxf(a0.y + a1.y, 0.f);
    o.z = fmaxf(a0.z + a1.z, 0.f); o.w = fmaxf(a0.w + a1.w, 0.f);
    ((float4*)out)[(size_t)n * 32 + lane] = o;
}

// ---------------- launch -----------------------------------------------------
extern "C" void kernel_launch(void* const* d_in, const int* in_sizes, int n_in,
                              void* d_out, int out_size) {
    const float* nodes   = (const float*)d_in[0];
    const int*   indices = (const int*)d_in[1];   // int32 (JAX x64 disabled)
    const float* values  = (const float*)d_in[2];
    const float* weights = (const float*)d_in[3];
    float*       out     = (float*)d_out;

    const int* rows = indices;
    const int* cols = indices + NNZ;

    // one-time side stream + events (created on the uncaptured correctness
    // call; per-call WORK is identical every launch)
    static cudaStream_t s_side = nullptr;
    static cudaEvent_t  ev_fork = nullptr, ev_join = nullptr;
    if (s_side == nullptr) {
        cudaStreamCreateWithFlags(&s_side, cudaStreamNonBlocking);
        cudaEventCreateWithFlags(&ev_fork, cudaEventDisableTiming);
        cudaEventCreateWithFlags(&ev_join, cudaEventDisableTiming);
        cudaFuncSetAttribute(k_gemm_tc,
                             cudaFuncAttributeMaxDynamicSharedMemorySize,
                             GEMM_SMEM);
    }

    // fork: side stream inherits capture dependency from the main stream
    cudaEventRecord(ev_fork, 0);
    cudaStreamWaitEvent(s_side, ev_fork, 0);

    // main stream: weight round + tensor-core pre-transform (fp16 out)
    k_wsplit<<<(RELS * HF * HT + 255) / 256, 256>>>(weights);
    k_gemm_tc<<<MBLK, 256, GEMM_SMEM>>>(nodes);

    // side stream: CSR-by-destination build (independent of GEMM)
    k_zero_deg<<<(DEGPAD / 4 + 255) / 256, 256, 0, s_side>>>();
    k_count<<<(NNZ + 255) / 256, 256, 0, s_side>>>(rows);
    k_scan<<<1, 1024, 0, s_side>>>();
    k_scatter<<<(NNZ + 255) / 256, 256, 0, s_side>>>(rows, cols, values);

    // join, then atomic-free aggregation + relu
    cudaEventRecord(ev_join, s_side);
    cudaStreamWaitEvent(0, ev_join, 0);
    k_gather<<<(NODES + 7) / 8, 256>>>(out);
}